// round 15
// baseline (speedup 1.0000x reference)
#include <cuda_runtime.h>
#include <cuda_fp16.h>
#include <cstdint>
#include <math.h>

#define NN 50000      // nodes
#define EE 800000     // raw edges
#define ET 850000     // edges + self loops
#define FH 128        // F_IN == NHID
#define NH 4          // heads
#define NC 64         // classes
#define SLOPE 0.2f

// ---------------- static device scratch (no runtime alloc allowed) ----------
static __device__ __half g_xsh[(size_t)NN * NH * FH];  // layer1 feats, [n][h*128+c]
static __device__ __half g_xh[(size_t)NN * NH * FH];   // layer1 out / layer2 in, [n][512]
static __device__ __half g_xs2h[(size_t)NN * NC];      // layer2 feats, fp16
static __device__ float  g_ssrc[NN * NH];              // interleaved [n*4+h]
static __device__ float  g_sdst[NN * NH];              // interleaved [n*4+h]
static __device__ float  g_ssrc2[NN];
static __device__ float  g_sdst2[NN];
static __device__ int    g_deg[NN];
static __device__ int    g_row[NN + 1];
static __device__ int    g_fill[NN];
static __device__ int    g_csrc[ET];

__device__ __forceinline__ float lrelu(float x) { return x > 0.f ? x : SLOPE * x; }

__device__ __forceinline__ void mma_f16(float* d, const uint32_t* a, const uint32_t* b) {
    asm volatile(
        "mma.sync.aligned.m16n8k16.row.col.f32.f16.f16.f32 "
        "{%0,%1,%2,%3}, {%4,%5,%6,%7}, {%8,%9}, {%0,%1,%2,%3};"
        : "+f"(d[0]), "+f"(d[1]), "+f"(d[2]), "+f"(d[3])
        : "r"(a[0]), "r"(a[1]), "r"(a[2]), "r"(a[3]), "r"(b[0]), "r"(b[1]));
}
__device__ __forceinline__ void ldsm_x4(uint32_t& r0, uint32_t& r1, uint32_t& r2,
                                        uint32_t& r3, uint32_t a) {
    asm volatile("ldmatrix.sync.aligned.m8n8.x4.shared.b16 {%0,%1,%2,%3}, [%4];"
                 : "=r"(r0), "=r"(r1), "=r"(r2), "=r"(r3) : "r"(a));
}
__device__ __forceinline__ void ldsm_x4_t(uint32_t& r0, uint32_t& r1, uint32_t& r2,
                                          uint32_t& r3, uint32_t a) {
    asm volatile("ldmatrix.sync.aligned.m8n8.x4.trans.shared.b16 {%0,%1,%2,%3}, [%4];"
                 : "=r"(r0), "=r"(r1), "=r"(r2), "=r"(r3) : "r"(a));
}
__device__ __forceinline__ uint32_t h2u(__half2 h) {
    return *reinterpret_cast<uint32_t*>(&h);
}
__device__ __forceinline__ int imin(int a, int b) { return a < b ? a : b; }

// ---------------- CSR build --------------------------------------------------
__global__ void count_kernel(const int* __restrict__ edge) {
    int e = blockIdx.x * blockDim.x + threadIdx.x;
    if (e >= ET) return;
    int d = (e < EE) ? edge[EE + e] : (e - EE);
    atomicAdd(&g_deg[d], 1);
}

#define SCAN_T 1024
__global__ void scan_kernel() {
    __shared__ int sh[SCAN_T];
    const int tid = threadIdx.x;
    const int CH = (NN + SCAN_T - 1) / SCAN_T;
    const int base = tid * CH;
    int sum = 0;
    for (int k = 0; k < CH; k++) {
        int i = base + k;
        if (i < NN) sum += g_deg[i];
    }
    sh[tid] = sum;
    __syncthreads();
    for (int off = 1; off < SCAN_T; off <<= 1) {
        int v = (tid >= off) ? sh[tid - off] : 0;
        __syncthreads();
        sh[tid] += v;
        __syncthreads();
    }
    int run = (tid == 0) ? 0 : sh[tid - 1];
    for (int k = 0; k < CH; k++) {
        int i = base + k;
        if (i < NN) {
            g_row[i] = run;
            g_fill[i] = run;
            run += g_deg[i];
        }
    }
    if (tid == SCAN_T - 1) g_row[NN] = run;
}

__global__ void fill_kernel(const int* __restrict__ edge) {
    int e = blockIdx.x * blockDim.x + threadIdx.x;
    if (e >= ET) return;
    int s, d;
    if (e < EE) { s = edge[e]; d = edge[EE + e]; } else { s = d = e - EE; }
    int pos = atomicAdd(&g_fill[d], 1);
    g_csrc[pos] = s;
}

// ---------------- layer-1 GEMM: single-stage full-K, 512 threads ------------
__global__ void __launch_bounds__(512, 2)
hgemm1_kernel(const float* __restrict__ A, const float* __restrict__ B,
              __half* __restrict__ Ch,
              float* __restrict__ dsrc, float* __restrict__ ddst,
              const float* __restrict__ atts, const float* __restrict__ attd) {
    constexpr int BM = 128;
    constexpr int KK = 128;
    constexpr int BN = 128;
    constexpr int AST = 136;
    constexpr int BST = 136;
    constexpr int MT = 2;
    constexpr int NT = 4;

    extern __shared__ __align__(16) char dyn[];
    __half* As = reinterpret_cast<__half*>(dyn);            // 34816 B
    __half* Bs = reinterpret_cast<__half*>(dyn + 34816);    // 34816 B
    float* sds = reinterpret_cast<float*>(dyn + 69632);     // 4*128 floats
    float* sdd = reinterpret_cast<float*>(dyn + 71680);     // 4*128 floats

    const int tid = threadIdx.x;
    const int lane = tid & 31;
    const int wid = tid >> 5;
    const int wm = wid >> 2;
    const int wn = wid & 3;
    const int r = lane >> 2;
    const int c = lane & 3;
    const int h = blockIdx.z;
    const int rowBase = blockIdx.x * BM;

    A    += (size_t)h * NN * FH;
    B    += (size_t)h * FH * FH;
    Ch   += (size_t)h * FH;        // column offset within [n][512]
    atts += h * FH;
    attd += h * FH;

    #pragma unroll 4
    for (int t = 0; t < 8; t++) {
        int idx = tid + t * 512;
        int rr = idx >> 5;
        int c4 = (idx & 31) * 4;
        float4 v = make_float4(0.f, 0.f, 0.f, 0.f);
        if (rowBase + rr < NN)
            v = *reinterpret_cast<const float4*>(&A[(size_t)(rowBase + rr) * KK + c4]);
        uint2 u = make_uint2(h2u(__floats2half2_rn(v.x, v.y)),
                             h2u(__floats2half2_rn(v.z, v.w)));
        *reinterpret_cast<uint2*>(&As[rr * AST + c4]) = u;
    }
    #pragma unroll 4
    for (int t = 0; t < 8; t++) {
        int idx = tid + t * 512;
        int rr = idx >> 5;
        int c4 = (idx & 31) * 4;
        float4 v = *reinterpret_cast<const float4*>(&B[(size_t)rr * BN + c4]);
        uint2 u = make_uint2(h2u(__floats2half2_rn(v.x, v.y)),
                             h2u(__floats2half2_rn(v.z, v.w)));
        *reinterpret_cast<uint2*>(&Bs[rr * BST + c4]) = u;
    }
    __syncthreads();

    float acc[MT][NT][4] = {};
    const int m = lane >> 3;
    const int i = lane & 7;
    #pragma unroll
    for (int kk = 0; kk < KK; kk += 16) {
        uint32_t af[MT][4];
        #pragma unroll
        for (int mt = 0; mt < MT; mt++) {
            int row = wm * 32 + mt * 16 + (m & 1) * 8 + i;
            int col = kk + (m >> 1) * 8;
            uint32_t addr = (uint32_t)__cvta_generic_to_shared(&As[row * AST + col]);
            ldsm_x4(af[mt][0], af[mt][1], af[mt][2], af[mt][3], addr);
        }
        uint32_t bf[NT][2];
        #pragma unroll
        for (int j = 0; j < NT / 2; j++) {
            int krow = kk + (m & 1) * 8 + i;
            int col = wn * 32 + j * 16 + (m >> 1) * 8;
            uint32_t addr = (uint32_t)__cvta_generic_to_shared(&Bs[krow * BST + col]);
            ldsm_x4_t(bf[2 * j][0], bf[2 * j][1], bf[2 * j + 1][0], bf[2 * j + 1][1], addr);
        }
        #pragma unroll
        for (int mt = 0; mt < MT; mt++)
            #pragma unroll
            for (int nt = 0; nt < NT; nt++)
                mma_f16(acc[mt][nt], af[mt], bf[nt]);
    }

    float pds[MT][2] = {}, pdd[MT][2] = {};
    #pragma unroll
    for (int mt = 0; mt < MT; mt++) {
        int row0 = rowBase + wm * 32 + mt * 16 + r;
        #pragma unroll
        for (int nt = 0; nt < NT; nt++) {
            int col0 = wn * 32 + nt * 8 + 2 * c;
            float as0 = __ldg(&atts[col0]), as1 = __ldg(&atts[col0 + 1]);
            float ad0 = __ldg(&attd[col0]), ad1 = __ldg(&attd[col0 + 1]);
            float* d = acc[mt][nt];
            pds[mt][0] += d[0] * as0 + d[1] * as1;
            pds[mt][1] += d[2] * as0 + d[3] * as1;
            pdd[mt][0] += d[0] * ad0 + d[1] * ad1;
            pdd[mt][1] += d[2] * ad0 + d[3] * ad1;
            if (row0 < NN)
                *reinterpret_cast<__half2*>(&Ch[(size_t)row0 * (NH * FH) + col0]) =
                    __floats2half2_rn(d[0], d[1]);
            if (row0 + 8 < NN)
                *reinterpret_cast<__half2*>(&Ch[(size_t)(row0 + 8) * (NH * FH) + col0]) =
                    __floats2half2_rn(d[2], d[3]);
        }
    }
    #pragma unroll
    for (int mt = 0; mt < MT; mt++) {
        #pragma unroll
        for (int hh = 0; hh < 2; hh++) {
            pds[mt][hh] += __shfl_xor_sync(0xffffffffu, pds[mt][hh], 1);
            pds[mt][hh] += __shfl_xor_sync(0xffffffffu, pds[mt][hh], 2);
            pdd[mt][hh] += __shfl_xor_sync(0xffffffffu, pdd[mt][hh], 1);
            pdd[mt][hh] += __shfl_xor_sync(0xffffffffu, pdd[mt][hh], 2);
        }
    }
    if (c == 0) {
        #pragma unroll
        for (int mt = 0; mt < MT; mt++) {
            int rloc = wm * 32 + mt * 16 + r;
            sds[wn * 128 + rloc] = pds[mt][0];
            sdd[wn * 128 + rloc] = pdd[mt][0];
            sds[wn * 128 + rloc + 8] = pds[mt][1];
            sdd[wn * 128 + rloc + 8] = pdd[mt][1];
        }
    }
    __syncthreads();
    if (tid < BM) {
        int row = rowBase + tid;
        if (row < NN) {
            dsrc[(size_t)row * NH + h] =
                sds[tid] + sds[128 + tid] + sds[256 + tid] + sds[384 + tid];
            ddst[(size_t)row * NH + h] =
                sdd[tid] + sdd[128 + tid] + sdd[256 + tid] + sdd[384 + tid];
        }
    }
}

// ---------------- layer-2 GEMM: fp16 A, double-buffered, fused dots ---------
__global__ void __launch_bounds__(256)
hgemm2_kernel(const __half* __restrict__ A16, const float* __restrict__ B,
              __half* __restrict__ Ch,
              float* __restrict__ dsrc, float* __restrict__ ddst,
              const float* __restrict__ atts, const float* __restrict__ attd,
              int M, int K) {
    constexpr int BM = 128;
    constexpr int BK = 32;
    constexpr int BN = 64;
    constexpr int WN = 32;
    constexpr int AST = 40;
    constexpr int BST = BN + 8;
    constexpr int MT = 2;
    constexpr int NT = WN / 8;
    constexpr int A_LD = BM * BK / (8 * 256);   // 2
    constexpr int B_LD = BK * BN / (4 * 256);   // 2

    __shared__ __align__(16) __half As[2][BM * AST];
    __shared__ __align__(16) __half Bs[2][BK * BST];
    __shared__ float sds[2][BM], sdd[2][BM];

    const int tid = threadIdx.x;
    const int lane = tid & 31;
    const int wid = tid >> 5;
    const int wm = wid >> 1;
    const int wn = wid & 1;
    const int r = lane >> 2;
    const int c = lane & 3;
    const int rowBase = blockIdx.x * BM;

    float acc[MT][NT][4] = {};
    uint4  aS16[A_LD];
    float4 bS[B_LD];

    auto stage = [&](int k0) {
        #pragma unroll
        for (int t = 0; t < A_LD; t++) {
            int idx = tid + t * 256;
            int rr = idx >> 2;
            int c8 = (idx & 3) * 8;
            aS16[t] = (rowBase + rr < M)
                ? *reinterpret_cast<const uint4*>(&A16[(size_t)(rowBase + rr) * K + k0 + c8])
                : make_uint4(0, 0, 0, 0);
        }
        #pragma unroll
        for (int t = 0; t < B_LD; t++) {
            int idx = tid + t * 256;
            int rr = idx / (BN / 4);
            int c4 = (idx % (BN / 4)) * 4;
            bS[t] = *reinterpret_cast<const float4*>(&B[(size_t)(k0 + rr) * BN + c4]);
        }
    };
    auto commit = [&](int buf) {
        #pragma unroll
        for (int t = 0; t < A_LD; t++) {
            int idx = tid + t * 256;
            int rr = idx >> 2;
            int c8 = (idx & 3) * 8;
            *reinterpret_cast<uint4*>(&As[buf][rr * AST + c8]) = aS16[t];
        }
        #pragma unroll
        for (int t = 0; t < B_LD; t++) {
            int idx = tid + t * 256;
            int rr = idx / (BN / 4);
            int c4 = (idx % (BN / 4)) * 4;
            uint2 u = make_uint2(h2u(__floats2half2_rn(bS[t].x, bS[t].y)),
                                 h2u(__floats2half2_rn(bS[t].z, bS[t].w)));
            *reinterpret_cast<uint2*>(&Bs[buf][rr * BST + c4]) = u;
        }
    };
    auto compute = [&](int buf) {
        const int m = lane >> 3;
        const int i = lane & 7;
        #pragma unroll
        for (int ks = 0; ks < BK / 16; ks++) {
            const int kk = ks * 16;
            uint32_t af[MT][4];
            #pragma unroll
            for (int mt = 0; mt < MT; mt++) {
                int row = wm * 32 + mt * 16 + (m & 1) * 8 + i;
                int col = kk + (m >> 1) * 8;
                uint32_t addr = (uint32_t)__cvta_generic_to_shared(&As[buf][row * AST + col]);
                ldsm_x4(af[mt][0], af[mt][1], af[mt][2], af[mt][3], addr);
            }
            uint32_t bf[NT][2];
            #pragma unroll
            for (int j = 0; j < NT / 2; j++) {
                int krow = kk + (m & 1) * 8 + i;
                int col = wn * WN + j * 16 + (m >> 1) * 8;
                uint32_t addr = (uint32_t)__cvta_generic_to_shared(&Bs[buf][krow * BST + col]);
                ldsm_x4_t(bf[2 * j][0], bf[2 * j][1], bf[2 * j + 1][0], bf[2 * j + 1][1], addr);
            }
            #pragma unroll
            for (int mt = 0; mt < MT; mt++)
                #pragma unroll
                for (int nt = 0; nt < NT; nt++)
                    mma_f16(acc[mt][nt], af[mt], bf[nt]);
        }
    };

    stage(0);
    commit(0);
    __syncthreads();
    int buf = 0;
    for (int k0 = 0; k0 < K; k0 += BK) {
        if (k0 + BK < K) {
            stage(k0 + BK);
            compute(buf);
            commit(buf ^ 1);
            __syncthreads();
            buf ^= 1;
        } else {
            compute(buf);
        }
    }

    float pds[MT][2] = {}, pdd[MT][2] = {};
    #pragma unroll
    for (int mt = 0; mt < MT; mt++) {
        int row0 = rowBase + wm * 32 + mt * 16 + r;
        #pragma unroll
        for (int nt = 0; nt < NT; nt++) {
            int col0 = wn * WN + nt * 8 + 2 * c;
            float as0 = __ldg(&atts[col0]), as1 = __ldg(&atts[col0 + 1]);
            float ad0 = __ldg(&attd[col0]), ad1 = __ldg(&attd[col0 + 1]);
            float* d = acc[mt][nt];
            pds[mt][0] += d[0] * as0 + d[1] * as1;
            pds[mt][1] += d[2] * as0 + d[3] * as1;
            pdd[mt][0] += d[0] * ad0 + d[1] * ad1;
            pdd[mt][1] += d[2] * ad0 + d[3] * ad1;
            if (row0 < M)
                *reinterpret_cast<__half2*>(&Ch[(size_t)row0 * BN + col0]) =
                    __floats2half2_rn(d[0], d[1]);
            if (row0 + 8 < M)
                *reinterpret_cast<__half2*>(&Ch[(size_t)(row0 + 8) * BN + col0]) =
                    __floats2half2_rn(d[2], d[3]);
        }
    }
    #pragma unroll
    for (int mt = 0; mt < MT; mt++) {
        #pragma unroll
        for (int hh = 0; hh < 2; hh++) {
            pds[mt][hh] += __shfl_xor_sync(0xffffffffu, pds[mt][hh], 1);
            pds[mt][hh] += __shfl_xor_sync(0xffffffffu, pds[mt][hh], 2);
            pdd[mt][hh] += __shfl_xor_sync(0xffffffffu, pdd[mt][hh], 1);
            pdd[mt][hh] += __shfl_xor_sync(0xffffffffu, pdd[mt][hh], 2);
        }
    }
    if (c == 0) {
        #pragma unroll
        for (int mt = 0; mt < MT; mt++) {
            int rloc = wm * 32 + mt * 16 + r;
            sds[wn][rloc] = pds[mt][0];
            sdd[wn][rloc] = pdd[mt][0];
            sds[wn][rloc + 8] = pds[mt][1];
            sdd[wn][rloc + 8] = pdd[mt][1];
        }
    }
    __syncthreads();
    if (tid < BM) {
        int row = rowBase + tid;
        if (row < M) {
            dsrc[row] = sds[0][tid] + sds[1][tid];
            ddst[row] = sdd[0][tid] + sdd[1][tid];
        }
    }
}

// ---------------- layer 1 fused gather: all 4 heads per warp ----------------
// Indices cached in warp registers (1 coalesced load / 32 edges, shfl lookup);
// payloads software-pipelined 2 deep with address known 2 iterations ahead.
__global__ void gather1_kernel(const float* __restrict__ bias) {
    long n = ((long)blockIdx.x * blockDim.x + threadIdx.x) >> 5;
    int lane = threadIdx.x & 31;
    if (n >= NN) return;

    const int beg = g_row[n];
    const int end = g_row[n + 1];
    const float4 sd = *reinterpret_cast<const float4*>(&g_sdst[(size_t)n * NH]);
    const float4* __restrict__ ss4 = reinterpret_cast<const float4*>(g_ssrc);
    const __half* __restrict__ xsh = g_xsh;
    const unsigned FULL = 0xffffffffu;

    // warp-register index cache: two 32-edge chunks
    int base = beg;
    int c0 = g_csrc[imin(beg + lane, end - 1)];
    int c1 = g_csrc[imin(beg + 32 + lane, end - 1)];

    float4 acc0 = make_float4(0.f, 0.f, 0.f, 0.f);
    float4 acc1 = acc0, acc2 = acc0, acc3 = acc0, den = acc0;

    // payload slots (depth 2)
    float4 ssl[2];
    uint2 u[2][4];

    auto idxat = [&](int jj) -> int {
        int rel = jj - base;
        return (rel < 32) ? __shfl_sync(FULL, c0, rel & 31)
                          : __shfl_sync(FULL, c1, rel & 31);
    };
    auto ldpay = [&](int slot, int s) {
        ssl[slot] = ss4[s];
        const __half* p = &xsh[(size_t)s * (NH * FH) + lane * 4];
        u[slot][0] = *reinterpret_cast<const uint2*>(p);
        u[slot][1] = *reinterpret_cast<const uint2*>(p + FH);
        u[slot][2] = *reinterpret_cast<const uint2*>(p + 2 * FH);
        u[slot][3] = *reinterpret_cast<const uint2*>(p + 3 * FH);
    };

    ldpay(0, idxat(beg));
    ldpay(1, idxat(imin(beg + 1, end - 1)));

    #pragma unroll 2
    for (int j = beg; j < end; j++) {
        if (j - base >= 32) {       // warp-uniform chunk rotation
            base += 32;
            c0 = c1;
            c1 = g_csrc[imin(base + 32 + lane, end - 1)];
        }
        const int slot = (j - beg) & 1;
        // consume current slot
        float4 ss = ssl[slot];
        uint2 v0 = u[slot][0], v1 = u[slot][1], v2 = u[slot][2], v3 = u[slot][3];
        // prefetch edge j+2 into the same slot (address known from reg cache)
        int jp = (j + 2 < end) ? j + 2 : j;
        ldpay(slot, idxat(jp));

        float e0 = __expf(lrelu(ss.x + sd.x));
        float e1 = __expf(lrelu(ss.y + sd.y));
        float e2 = __expf(lrelu(ss.z + sd.z));
        float e3 = __expf(lrelu(ss.w + sd.w));
        den.x += e0; den.y += e1; den.z += e2; den.w += e3;

        float2 f;
        f = __half22float2(*reinterpret_cast<__half2*>(&v0.x)); acc0.x += e0 * f.x; acc0.y += e0 * f.y;
        f = __half22float2(*reinterpret_cast<__half2*>(&v0.y)); acc0.z += e0 * f.x; acc0.w += e0 * f.y;
        f = __half22float2(*reinterpret_cast<__half2*>(&v1.x)); acc1.x += e1 * f.x; acc1.y += e1 * f.y;
        f = __half22float2(*reinterpret_cast<__half2*>(&v1.y)); acc1.z += e1 * f.x; acc1.w += e1 * f.y;
        f = __half22float2(*reinterpret_cast<__half2*>(&v2.x)); acc2.x += e2 * f.x; acc2.y += e2 * f.y;
        f = __half22float2(*reinterpret_cast<__half2*>(&v2.y)); acc2.z += e2 * f.x; acc2.w += e2 * f.y;
        f = __half22float2(*reinterpret_cast<__half2*>(&v3.x)); acc3.x += e3 * f.x; acc3.y += e3 * f.y;
        f = __half22float2(*reinterpret_cast<__half2*>(&v3.y)); acc3.z += e3 * f.x; acc3.w += e3 * f.y;
    }

    __half* __restrict__ xo = &g_xh[(size_t)n * (NH * FH) + lane * 4];
    const float inv0 = 1.f / den.x, inv1 = 1.f / den.y;
    const float inv2 = 1.f / den.z, inv3 = 1.f / den.w;
    float4 b;
    uint2 o;
    b = *reinterpret_cast<const float4*>(&bias[0 * FH + lane * 4]);
    o.x = h2u(__floats2half2_rn(lrelu(acc0.x * inv0 + b.x), lrelu(acc0.y * inv0 + b.y)));
    o.y = h2u(__floats2half2_rn(lrelu(acc0.z * inv0 + b.z), lrelu(acc0.w * inv0 + b.w)));
    *reinterpret_cast<uint2*>(&xo[0 * FH]) = o;
    b = *reinterpret_cast<const float4*>(&bias[1 * FH + lane * 4]);
    o.x = h2u(__floats2half2_rn(lrelu(acc1.x * inv1 + b.x), lrelu(acc1.y * inv1 + b.y)));
    o.y = h2u(__floats2half2_rn(lrelu(acc1.z * inv1 + b.z), lrelu(acc1.w * inv1 + b.w)));
    *reinterpret_cast<uint2*>(&xo[1 * FH]) = o;
    b = *reinterpret_cast<const float4*>(&bias[2 * FH + lane * 4]);
    o.x = h2u(__floats2half2_rn(lrelu(acc2.x * inv2 + b.x), lrelu(acc2.y * inv2 + b.y)));
    o.y = h2u(__floats2half2_rn(lrelu(acc2.z * inv2 + b.z), lrelu(acc2.w * inv2 + b.w)));
    *reinterpret_cast<uint2*>(&xo[2 * FH]) = o;
    b = *reinterpret_cast<const float4*>(&bias[3 * FH + lane * 4]);
    o.x = h2u(__floats2half2_rn(lrelu(acc3.x * inv3 + b.x), lrelu(acc3.y * inv3 + b.y)));
    o.y = h2u(__floats2half2_rn(lrelu(acc3.z * inv3 + b.z), lrelu(acc3.w * inv3 + b.w)));
    *reinterpret_cast<uint2*>(&xo[3 * FH]) = o;
}

// ---------------- layer 2 fused gather: same reg-cached index scheme --------
__global__ void gather2_kernel(float* __restrict__ out, const float* __restrict__ bias_out) {
    long n = ((long)blockIdx.x * blockDim.x + threadIdx.x) >> 5;
    int lane = threadIdx.x & 31;
    if (n >= NN) return;

    const int beg = g_row[n];
    const int end = g_row[n + 1];
    const float sd = g_sdst2[n];
    const unsigned FULL = 0xffffffffu;

    int base = beg;
    int c0 = g_csrc[imin(beg + lane, end - 1)];
    int c1 = g_csrc[imin(beg + 32 + lane, end - 1)];

    float2 acc = make_float2(0.f, 0.f);
    float den = 0.f;

    float ssl[2];
    __half2 hvl[2];

    auto idxat = [&](int jj) -> int {
        int rel = jj - base;
        return (rel < 32) ? __shfl_sync(FULL, c0, rel & 31)
                          : __shfl_sync(FULL, c1, rel & 31);
    };
    auto ldpay = [&](int slot, int s) {
        ssl[slot] = g_ssrc2[s];
        hvl[slot] = *reinterpret_cast<const __half2*>(&g_xs2h[(size_t)s * NC + lane * 2]);
    };

    ldpay(0, idxat(beg));
    ldpay(1, idxat(imin(beg + 1, end - 1)));

    #pragma unroll 2
    for (int j = beg; j < end; j++) {
        if (j - base >= 32) {
            base += 32;
            c0 = c1;
            c1 = g_csrc[imin(base + 32 + lane, end - 1)];
        }
        const int slot = (j - beg) & 1;
        float ss = ssl[slot];
        __half2 hv = hvl[slot];
        int jp = (j + 2 < end) ? j + 2 : j;
        ldpay(slot, idxat(jp));

        float ex = __expf(lrelu(ss + sd));
        float2 v = __half22float2(hv);
        den += ex;
        acc.x += ex * v.x; acc.y += ex * v.y;
    }
    const float inv = 1.f / den;
    const float2 b = *reinterpret_cast<const float2*>(&bias_out[lane * 2]);
    float2 o;
    o.x = tanhf(lrelu(acc.x * inv + b.x));
    o.y = tanhf(lrelu(acc.y * inv + b.y));
    *reinterpret_cast<float2*>(&out[(size_t)n * NC + lane * 2]) = o;
}

// ---------------- launch ----------------------------------------------------
extern "C" void kernel_launch(void* const* d_in, const int* in_sizes, int n_in,
                              void* d_out, int out_size) {
    const float* type_emb  = (const float*)d_in[0];  // [4,50000,128]
    const int*   edge      = (const int*)d_in[1];    // [2,800000]
    const float* W         = (const float*)d_in[2];  // [4,128,128]
    const float* att_src   = (const float*)d_in[3];  // [4,128]
    const float* att_dst   = (const float*)d_in[4];  // [4,128]
    const float* bias      = (const float*)d_in[5];  // [4,128]
    const float* W_out     = (const float*)d_in[6];  // [512,64]
    const float* att_src_o = (const float*)d_in[7];  // [64]
    const float* att_dst_o = (const float*)d_in[8];  // [64]
    const float* bias_o    = (const float*)d_in[9];  // [64]
    float* out = (float*)d_out;                      // [50000,64]
    (void)in_sizes; (void)n_in; (void)out_size;

    __half *p_xsh, *p_xh, *p_xs2h;
    float *p_ssrc, *p_sdst, *p_ssrc2, *p_sdst2;
    int *p_deg;
    cudaGetSymbolAddress((void**)&p_xsh, g_xsh);
    cudaGetSymbolAddress((void**)&p_xh, g_xh);
    cudaGetSymbolAddress((void**)&p_xs2h, g_xs2h);
    cudaGetSymbolAddress((void**)&p_ssrc, g_ssrc);
    cudaGetSymbolAddress((void**)&p_sdst, g_sdst);
    cudaGetSymbolAddress((void**)&p_ssrc2, g_ssrc2);
    cudaGetSymbolAddress((void**)&p_sdst2, g_sdst2);
    cudaGetSymbolAddress((void**)&p_deg, g_deg);

    constexpr int GEMM1_SMEM = 73728;   // 2*34816 + 2*2048

    // one-time host objects (created on the uncaptured correctness call)
    static cudaStream_t s_side = nullptr;
    static cudaEvent_t ev_fork = nullptr, ev_join = nullptr;
    if (s_side == nullptr) {
        cudaStreamCreateWithFlags(&s_side, cudaStreamNonBlocking);
        cudaEventCreateWithFlags(&ev_fork, cudaEventDisableTiming);
        cudaEventCreateWithFlags(&ev_join, cudaEventDisableTiming);
        cudaFuncSetAttribute(hgemm1_kernel,
                             cudaFuncAttributeMaxDynamicSharedMemorySize, GEMM1_SMEM);
    }

    // ---- fork: CSR build on side stream, overlapped with layer-1 GEMM ----
    cudaEventRecord(ev_fork, 0);
    cudaStreamWaitEvent(s_side, ev_fork, 0);
    cudaMemsetAsync(p_deg, 0, NN * sizeof(int), s_side);
    count_kernel<<<(ET + 255) / 256, 256, 0, s_side>>>(edge);
    scan_kernel<<<1, SCAN_T, 0, s_side>>>();
    fill_kernel<<<(ET + 255) / 256, 256, 0, s_side>>>(edge);
    cudaEventRecord(ev_join, s_side);

    // ---- Layer 1 GEMM (single-stage full-K, 512 thr, fused dots) ----
    dim3 g1((NN + 127) / 128, 1, NH);
    hgemm1_kernel<<<g1, 512, GEMM1_SMEM>>>(
        type_emb, W, p_xsh, p_ssrc, p_sdst, att_src, att_dst);

    // ---- join: gather needs CSR + GEMM ----
    cudaStreamWaitEvent(0, ev_join, 0);

    gather1_kernel<<<(int)(((long)NN * 32 + 255) / 256), 256>>>(bias);

    // ---- Layer 2: fp16 A GEMM, then gather ----
    dim3 g2((NN + 127) / 128, 1, 1);
    hgemm2_kernel<<<g2, 256>>>(
        p_xh, W_out, p_xs2h, p_ssrc2, p_sdst2, att_src_o, att_dst_o,
        NN, NH * FH);

    gather2_kernel<<<(NN * 32 + 255) / 256, 256>>>(out, bias_o);
}

// round 17
// speedup vs baseline: 1.0559x; 1.0559x over previous
#include <cuda_runtime.h>
#include <cuda_fp16.h>
#include <cstdint>
#include <math.h>

#define NN 50000      // nodes
#define EE 800000     // raw edges
#define ET 850000     // edges + self loops
#define FH 128        // F_IN == NHID
#define NH 4          // heads
#define NC 64         // classes
#define SLOPE 0.2f

// ---------------- static device scratch (no runtime alloc allowed) ----------
static __device__ __half g_xsh[(size_t)NN * NH * FH];  // layer1 feats, [n][h*128+c]
static __device__ __half g_xh[(size_t)NN * NH * FH];   // layer1 out / layer2 in, [n][512]
static __device__ __half g_xs2h[(size_t)NN * NC];      // layer2 feats, fp16
static __device__ float  g_ssrc[NN * NH];              // interleaved [n*4+h]
static __device__ float  g_sdst[NN * NH];              // interleaved [n*4+h]
static __device__ float  g_ssrc2[NN];
static __device__ float  g_sdst2[NN];
static __device__ int    g_deg[NN];
static __device__ int    g_row[NN + 1];
static __device__ int    g_fill[NN];
static __device__ int    g_csrc[ET];

__device__ __forceinline__ float lrelu(float x) { return x > 0.f ? x : SLOPE * x; }

__device__ __forceinline__ void mma_f16(float* d, const uint32_t* a, const uint32_t* b) {
    asm volatile(
        "mma.sync.aligned.m16n8k16.row.col.f32.f16.f16.f32 "
        "{%0,%1,%2,%3}, {%4,%5,%6,%7}, {%8,%9}, {%0,%1,%2,%3};"
        : "+f"(d[0]), "+f"(d[1]), "+f"(d[2]), "+f"(d[3])
        : "r"(a[0]), "r"(a[1]), "r"(a[2]), "r"(a[3]), "r"(b[0]), "r"(b[1]));
}
__device__ __forceinline__ void ldsm_x4(uint32_t& r0, uint32_t& r1, uint32_t& r2,
                                        uint32_t& r3, uint32_t a) {
    asm volatile("ldmatrix.sync.aligned.m8n8.x4.shared.b16 {%0,%1,%2,%3}, [%4];"
                 : "=r"(r0), "=r"(r1), "=r"(r2), "=r"(r3) : "r"(a));
}
__device__ __forceinline__ void ldsm_x4_t(uint32_t& r0, uint32_t& r1, uint32_t& r2,
                                          uint32_t& r3, uint32_t a) {
    asm volatile("ldmatrix.sync.aligned.m8n8.x4.trans.shared.b16 {%0,%1,%2,%3}, [%4];"
                 : "=r"(r0), "=r"(r1), "=r"(r2), "=r"(r3) : "r"(a));
}
__device__ __forceinline__ uint32_t h2u(__half2 h) {
    return *reinterpret_cast<uint32_t*>(&h);
}
__device__ __forceinline__ int imin(int a, int b) { return a < b ? a : b; }

// ---------------- CSR build --------------------------------------------------
__global__ void count_kernel(const int* __restrict__ edge) {
    int e = blockIdx.x * blockDim.x + threadIdx.x;
    if (e >= ET) return;
    int d = (e < EE) ? edge[EE + e] : (e - EE);
    atomicAdd(&g_deg[d], 1);
}

#define SCAN_T 1024
__global__ void scan_kernel() {
    __shared__ int sh[SCAN_T];
    const int tid = threadIdx.x;
    const int CH = (NN + SCAN_T - 1) / SCAN_T;
    const int base = tid * CH;
    int sum = 0;
    for (int k = 0; k < CH; k++) {
        int i = base + k;
        if (i < NN) sum += g_deg[i];
    }
    sh[tid] = sum;
    __syncthreads();
    for (int off = 1; off < SCAN_T; off <<= 1) {
        int v = (tid >= off) ? sh[tid - off] : 0;
        __syncthreads();
        sh[tid] += v;
        __syncthreads();
    }
    int run = (tid == 0) ? 0 : sh[tid - 1];
    for (int k = 0; k < CH; k++) {
        int i = base + k;
        if (i < NN) {
            g_row[i] = run;
            g_fill[i] = run;
            run += g_deg[i];
        }
    }
    if (tid == SCAN_T - 1) g_row[NN] = run;
}

__global__ void fill_kernel(const int* __restrict__ edge) {
    int e = blockIdx.x * blockDim.x + threadIdx.x;
    if (e >= ET) return;
    int s, d;
    if (e < EE) { s = edge[e]; d = edge[EE + e]; } else { s = d = e - EE; }
    int pos = atomicAdd(&g_fill[d], 1);
    g_csrc[pos] = s;
}

// ---------------- layer-1 GEMM: single-stage full-K, 512 threads ------------
__global__ void __launch_bounds__(512, 2)
hgemm1_kernel(const float* __restrict__ A, const float* __restrict__ B,
              __half* __restrict__ Ch,
              float* __restrict__ dsrc, float* __restrict__ ddst,
              const float* __restrict__ atts, const float* __restrict__ attd) {
    constexpr int BM = 128;
    constexpr int KK = 128;
    constexpr int BN = 128;
    constexpr int AST = 136;
    constexpr int BST = 136;
    constexpr int MT = 2;
    constexpr int NT = 4;

    extern __shared__ __align__(16) char dyn[];
    __half* As = reinterpret_cast<__half*>(dyn);            // 34816 B
    __half* Bs = reinterpret_cast<__half*>(dyn + 34816);    // 34816 B
    float* sds = reinterpret_cast<float*>(dyn + 69632);     // 4*128 floats
    float* sdd = reinterpret_cast<float*>(dyn + 71680);     // 4*128 floats

    const int tid = threadIdx.x;
    const int lane = tid & 31;
    const int wid = tid >> 5;
    const int wm = wid >> 2;
    const int wn = wid & 3;
    const int r = lane >> 2;
    const int c = lane & 3;
    const int h = blockIdx.z;
    const int rowBase = blockIdx.x * BM;

    A    += (size_t)h * NN * FH;
    B    += (size_t)h * FH * FH;
    Ch   += (size_t)h * FH;        // column offset within [n][512]
    atts += h * FH;
    attd += h * FH;

    #pragma unroll 4
    for (int t = 0; t < 8; t++) {
        int idx = tid + t * 512;
        int rr = idx >> 5;
        int c4 = (idx & 31) * 4;
        float4 v = make_float4(0.f, 0.f, 0.f, 0.f);
        if (rowBase + rr < NN)
            v = *reinterpret_cast<const float4*>(&A[(size_t)(rowBase + rr) * KK + c4]);
        uint2 u = make_uint2(h2u(__floats2half2_rn(v.x, v.y)),
                             h2u(__floats2half2_rn(v.z, v.w)));
        *reinterpret_cast<uint2*>(&As[rr * AST + c4]) = u;
    }
    #pragma unroll 4
    for (int t = 0; t < 8; t++) {
        int idx = tid + t * 512;
        int rr = idx >> 5;
        int c4 = (idx & 31) * 4;
        float4 v = *reinterpret_cast<const float4*>(&B[(size_t)rr * BN + c4]);
        uint2 u = make_uint2(h2u(__floats2half2_rn(v.x, v.y)),
                             h2u(__floats2half2_rn(v.z, v.w)));
        *reinterpret_cast<uint2*>(&Bs[rr * BST + c4]) = u;
    }
    __syncthreads();

    float acc[MT][NT][4] = {};
    const int m = lane >> 3;
    const int i = lane & 7;
    #pragma unroll
    for (int kk = 0; kk < KK; kk += 16) {
        uint32_t af[MT][4];
        #pragma unroll
        for (int mt = 0; mt < MT; mt++) {
            int row = wm * 32 + mt * 16 + (m & 1) * 8 + i;
            int col = kk + (m >> 1) * 8;
            uint32_t addr = (uint32_t)__cvta_generic_to_shared(&As[row * AST + col]);
            ldsm_x4(af[mt][0], af[mt][1], af[mt][2], af[mt][3], addr);
        }
        uint32_t bf[NT][2];
        #pragma unroll
        for (int j = 0; j < NT / 2; j++) {
            int krow = kk + (m & 1) * 8 + i;
            int col = wn * 32 + j * 16 + (m >> 1) * 8;
            uint32_t addr = (uint32_t)__cvta_generic_to_shared(&Bs[krow * BST + col]);
            ldsm_x4_t(bf[2 * j][0], bf[2 * j][1], bf[2 * j + 1][0], bf[2 * j + 1][1], addr);
        }
        #pragma unroll
        for (int mt = 0; mt < MT; mt++)
            #pragma unroll
            for (int nt = 0; nt < NT; nt++)
                mma_f16(acc[mt][nt], af[mt], bf[nt]);
    }

    float pds[MT][2] = {}, pdd[MT][2] = {};
    #pragma unroll
    for (int mt = 0; mt < MT; mt++) {
        int row0 = rowBase + wm * 32 + mt * 16 + r;
        #pragma unroll
        for (int nt = 0; nt < NT; nt++) {
            int col0 = wn * 32 + nt * 8 + 2 * c;
            float as0 = __ldg(&atts[col0]), as1 = __ldg(&atts[col0 + 1]);
            float ad0 = __ldg(&attd[col0]), ad1 = __ldg(&attd[col0 + 1]);
            float* d = acc[mt][nt];
            pds[mt][0] += d[0] * as0 + d[1] * as1;
            pds[mt][1] += d[2] * as0 + d[3] * as1;
            pdd[mt][0] += d[0] * ad0 + d[1] * ad1;
            pdd[mt][1] += d[2] * ad0 + d[3] * ad1;
            if (row0 < NN)
                *reinterpret_cast<__half2*>(&Ch[(size_t)row0 * (NH * FH) + col0]) =
                    __floats2half2_rn(d[0], d[1]);
            if (row0 + 8 < NN)
                *reinterpret_cast<__half2*>(&Ch[(size_t)(row0 + 8) * (NH * FH) + col0]) =
                    __floats2half2_rn(d[2], d[3]);
        }
    }
    #pragma unroll
    for (int mt = 0; mt < MT; mt++) {
        #pragma unroll
        for (int hh = 0; hh < 2; hh++) {
            pds[mt][hh] += __shfl_xor_sync(0xffffffffu, pds[mt][hh], 1);
            pds[mt][hh] += __shfl_xor_sync(0xffffffffu, pds[mt][hh], 2);
            pdd[mt][hh] += __shfl_xor_sync(0xffffffffu, pdd[mt][hh], 1);
            pdd[mt][hh] += __shfl_xor_sync(0xffffffffu, pdd[mt][hh], 2);
        }
    }
    if (c == 0) {
        #pragma unroll
        for (int mt = 0; mt < MT; mt++) {
            int rloc = wm * 32 + mt * 16 + r;
            sds[wn * 128 + rloc] = pds[mt][0];
            sdd[wn * 128 + rloc] = pdd[mt][0];
            sds[wn * 128 + rloc + 8] = pds[mt][1];
            sdd[wn * 128 + rloc + 8] = pdd[mt][1];
        }
    }
    __syncthreads();
    if (tid < BM) {
        int row = rowBase + tid;
        if (row < NN) {
            dsrc[(size_t)row * NH + h] =
                sds[tid] + sds[128 + tid] + sds[256 + tid] + sds[384 + tid];
            ddst[(size_t)row * NH + h] =
                sdd[tid] + sdd[128 + tid] + sdd[256 + tid] + sdd[384 + tid];
        }
    }
}

// ---------------- layer-2 GEMM: fp16 A, double-buffered, fused dots ---------
__global__ void __launch_bounds__(256)
hgemm2_kernel(const __half* __restrict__ A16, const float* __restrict__ B,
              __half* __restrict__ Ch,
              float* __restrict__ dsrc, float* __restrict__ ddst,
              const float* __restrict__ atts, const float* __restrict__ attd,
              int M, int K) {
    constexpr int BM = 128;
    constexpr int BK = 32;
    constexpr int BN = 64;
    constexpr int WN = 32;
    constexpr int AST = 40;
    constexpr int BST = BN + 8;
    constexpr int MT = 2;
    constexpr int NT = WN / 8;
    constexpr int A_LD = BM * BK / (8 * 256);   // 2
    constexpr int B_LD = BK * BN / (4 * 256);   // 2

    __shared__ __align__(16) __half As[2][BM * AST];
    __shared__ __align__(16) __half Bs[2][BK * BST];
    __shared__ float sds[2][BM], sdd[2][BM];

    const int tid = threadIdx.x;
    const int lane = tid & 31;
    const int wid = tid >> 5;
    const int wm = wid >> 1;
    const int wn = wid & 1;
    const int r = lane >> 2;
    const int c = lane & 3;
    const int rowBase = blockIdx.x * BM;

    float acc[MT][NT][4] = {};
    uint4  aS16[A_LD];
    float4 bS[B_LD];

    auto stage = [&](int k0) {
        #pragma unroll
        for (int t = 0; t < A_LD; t++) {
            int idx = tid + t * 256;
            int rr = idx >> 2;
            int c8 = (idx & 3) * 8;
            aS16[t] = (rowBase + rr < M)
                ? *reinterpret_cast<const uint4*>(&A16[(size_t)(rowBase + rr) * K + k0 + c8])
                : make_uint4(0, 0, 0, 0);
        }
        #pragma unroll
        for (int t = 0; t < B_LD; t++) {
            int idx = tid + t * 256;
            int rr = idx / (BN / 4);
            int c4 = (idx % (BN / 4)) * 4;
            bS[t] = *reinterpret_cast<const float4*>(&B[(size_t)(k0 + rr) * BN + c4]);
        }
    };
    auto commit = [&](int buf) {
        #pragma unroll
        for (int t = 0; t < A_LD; t++) {
            int idx = tid + t * 256;
            int rr = idx >> 2;
            int c8 = (idx & 3) * 8;
            *reinterpret_cast<uint4*>(&As[buf][rr * AST + c8]) = aS16[t];
        }
        #pragma unroll
        for (int t = 0; t < B_LD; t++) {
            int idx = tid + t * 256;
            int rr = idx / (BN / 4);
            int c4 = (idx % (BN / 4)) * 4;
            uint2 u = make_uint2(h2u(__floats2half2_rn(bS[t].x, bS[t].y)),
                                 h2u(__floats2half2_rn(bS[t].z, bS[t].w)));
            *reinterpret_cast<uint2*>(&Bs[buf][rr * BST + c4]) = u;
        }
    };
    auto compute = [&](int buf) {
        const int m = lane >> 3;
        const int i = lane & 7;
        #pragma unroll
        for (int ks = 0; ks < BK / 16; ks++) {
            const int kk = ks * 16;
            uint32_t af[MT][4];
            #pragma unroll
            for (int mt = 0; mt < MT; mt++) {
                int row = wm * 32 + mt * 16 + (m & 1) * 8 + i;
                int col = kk + (m >> 1) * 8;
                uint32_t addr = (uint32_t)__cvta_generic_to_shared(&As[buf][row * AST + col]);
                ldsm_x4(af[mt][0], af[mt][1], af[mt][2], af[mt][3], addr);
            }
            uint32_t bf[NT][2];
            #pragma unroll
            for (int j = 0; j < NT / 2; j++) {
                int krow = kk + (m & 1) * 8 + i;
                int col = wn * WN + j * 16 + (m >> 1) * 8;
                uint32_t addr = (uint32_t)__cvta_generic_to_shared(&Bs[buf][krow * BST + col]);
                ldsm_x4_t(bf[2 * j][0], bf[2 * j][1], bf[2 * j + 1][0], bf[2 * j + 1][1], addr);
            }
            #pragma unroll
            for (int mt = 0; mt < MT; mt++)
                #pragma unroll
                for (int nt = 0; nt < NT; nt++)
                    mma_f16(acc[mt][nt], af[mt], bf[nt]);
        }
    };

    stage(0);
    commit(0);
    __syncthreads();
    int buf = 0;
    for (int k0 = 0; k0 < K; k0 += BK) {
        if (k0 + BK < K) {
            stage(k0 + BK);
            compute(buf);
            commit(buf ^ 1);
            __syncthreads();
            buf ^= 1;
        } else {
            compute(buf);
        }
    }

    float pds[MT][2] = {}, pdd[MT][2] = {};
    #pragma unroll
    for (int mt = 0; mt < MT; mt++) {
        int row0 = rowBase + wm * 32 + mt * 16 + r;
        #pragma unroll
        for (int nt = 0; nt < NT; nt++) {
            int col0 = wn * WN + nt * 8 + 2 * c;
            float as0 = __ldg(&atts[col0]), as1 = __ldg(&atts[col0 + 1]);
            float ad0 = __ldg(&attd[col0]), ad1 = __ldg(&attd[col0 + 1]);
            float* d = acc[mt][nt];
            pds[mt][0] += d[0] * as0 + d[1] * as1;
            pds[mt][1] += d[2] * as0 + d[3] * as1;
            pdd[mt][0] += d[0] * ad0 + d[1] * ad1;
            pdd[mt][1] += d[2] * ad0 + d[3] * ad1;
            if (row0 < M)
                *reinterpret_cast<__half2*>(&Ch[(size_t)row0 * BN + col0]) =
                    __floats2half2_rn(d[0], d[1]);
            if (row0 + 8 < M)
                *reinterpret_cast<__half2*>(&Ch[(size_t)(row0 + 8) * BN + col0]) =
                    __floats2half2_rn(d[2], d[3]);
        }
    }
    #pragma unroll
    for (int mt = 0; mt < MT; mt++) {
        #pragma unroll
        for (int hh = 0; hh < 2; hh++) {
            pds[mt][hh] += __shfl_xor_sync(0xffffffffu, pds[mt][hh], 1);
            pds[mt][hh] += __shfl_xor_sync(0xffffffffu, pds[mt][hh], 2);
            pdd[mt][hh] += __shfl_xor_sync(0xffffffffu, pdd[mt][hh], 1);
            pdd[mt][hh] += __shfl_xor_sync(0xffffffffu, pdd[mt][hh], 2);
        }
    }
    if (c == 0) {
        #pragma unroll
        for (int mt = 0; mt < MT; mt++) {
            int rloc = wm * 32 + mt * 16 + r;
            sds[wn][rloc] = pds[mt][0];
            sdd[wn][rloc] = pdd[mt][0];
            sds[wn][rloc + 8] = pds[mt][1];
            sdd[wn][rloc + 8] = pdd[mt][1];
        }
    }
    __syncthreads();
    if (tid < BM) {
        int row = rowBase + tid;
        if (row < M) {
            dsrc[row] = sds[0][tid] + sds[1][tid];
            ddst[row] = sdd[0][tid] + sdd[1][tid];
        }
    }
}

// ---------------- layer 1 fused gather: all 4 heads per warp ----------------
// Plain broadcast index loads (NO shuffles); index pipeline depth 3, payload
// prefetch distance 2 so index->payload dependence has 2 iterations of slack.
__global__ void gather1_kernel(const float* __restrict__ bias) {
    long n = ((long)blockIdx.x * blockDim.x + threadIdx.x) >> 5;
    int lane = threadIdx.x & 31;
    if (n >= NN) return;

    const int beg = g_row[n];
    const int end = g_row[n + 1];
    const float4 sd = *reinterpret_cast<const float4*>(&g_sdst[(size_t)n * NH]);
    const float4* __restrict__ ss4 = reinterpret_cast<const float4*>(g_ssrc);
    const __half* __restrict__ xsh = g_xsh;

    float4 acc0 = make_float4(0.f, 0.f, 0.f, 0.f);
    float4 acc1 = acc0, acc2 = acc0, acc3 = acc0, den = acc0;

    // payload slots (depth 2)
    float4 ssl[2];
    uint2 u[2][4];
    auto ldpay = [&](int slot, int s) {
        ssl[slot] = ss4[s];
        const __half* p = &xsh[(size_t)s * (NH * FH) + lane * 4];
        u[slot][0] = *reinterpret_cast<const uint2*>(p);
        u[slot][1] = *reinterpret_cast<const uint2*>(p + FH);
        u[slot][2] = *reinterpret_cast<const uint2*>(p + 2 * FH);
        u[slot][3] = *reinterpret_cast<const uint2*>(p + 3 * FH);
    };

    // prime: indices for j, j+1, j+2 (broadcast loads); payloads for j, j+1
    int i0 = g_csrc[beg];
    int i1 = (beg + 1 < end) ? g_csrc[beg + 1] : i0;
    int i2 = (beg + 2 < end) ? g_csrc[beg + 2] : i1;
    ldpay(0, i0);
    ldpay(1, i1);

    for (int j = beg; j < end; j++) {
        const int slot = (j - beg) & 1;
        // consume current slot into locals before overwriting
        float4 ss = ssl[slot];
        uint2 v0 = u[slot][0], v1 = u[slot][1], v2 = u[slot][2], v3 = u[slot][3];
        // prefetch payload for j+2 using i2 (index loaded 2 iterations ago)
        ldpay(slot, i2);
        // rotate index pipeline; load index for j+3 (plain broadcast)
        i0 = i1; i1 = i2;
        i2 = (j + 3 < end) ? g_csrc[j + 3] : i2;

        float e0 = __expf(lrelu(ss.x + sd.x));
        float e1 = __expf(lrelu(ss.y + sd.y));
        float e2 = __expf(lrelu(ss.z + sd.z));
        float e3 = __expf(lrelu(ss.w + sd.w));
        den.x += e0; den.y += e1; den.z += e2; den.w += e3;

        float2 f;
        f = __half22float2(*reinterpret_cast<__half2*>(&v0.x)); acc0.x += e0 * f.x; acc0.y += e0 * f.y;
        f = __half22float2(*reinterpret_cast<__half2*>(&v0.y)); acc0.z += e0 * f.x; acc0.w += e0 * f.y;
        f = __half22float2(*reinterpret_cast<__half2*>(&v1.x)); acc1.x += e1 * f.x; acc1.y += e1 * f.y;
        f = __half22float2(*reinterpret_cast<__half2*>(&v1.y)); acc1.z += e1 * f.x; acc1.w += e1 * f.y;
        f = __half22float2(*reinterpret_cast<__half2*>(&v2.x)); acc2.x += e2 * f.x; acc2.y += e2 * f.y;
        f = __half22float2(*reinterpret_cast<__half2*>(&v2.y)); acc2.z += e2 * f.x; acc2.w += e2 * f.y;
        f = __half22float2(*reinterpret_cast<__half2*>(&v3.x)); acc3.x += e3 * f.x; acc3.y += e3 * f.y;
        f = __half22float2(*reinterpret_cast<__half2*>(&v3.y)); acc3.z += e3 * f.x; acc3.w += e3 * f.y;
    }

    __half* __restrict__ xo = &g_xh[(size_t)n * (NH * FH) + lane * 4];
    const float inv0 = 1.f / den.x, inv1 = 1.f / den.y;
    const float inv2 = 1.f / den.z, inv3 = 1.f / den.w;
    float4 b;
    uint2 o;
    b = *reinterpret_cast<const float4*>(&bias[0 * FH + lane * 4]);
    o.x = h2u(__floats2half2_rn(lrelu(acc0.x * inv0 + b.x), lrelu(acc0.y * inv0 + b.y)));
    o.y = h2u(__floats2half2_rn(lrelu(acc0.z * inv0 + b.z), lrelu(acc0.w * inv0 + b.w)));
    *reinterpret_cast<uint2*>(&xo[0 * FH]) = o;
    b = *reinterpret_cast<const float4*>(&bias[1 * FH + lane * 4]);
    o.x = h2u(__floats2half2_rn(lrelu(acc1.x * inv1 + b.x), lrelu(acc1.y * inv1 + b.y)));
    o.y = h2u(__floats2half2_rn(lrelu(acc1.z * inv1 + b.z), lrelu(acc1.w * inv1 + b.w)));
    *reinterpret_cast<uint2*>(&xo[1 * FH]) = o;
    b = *reinterpret_cast<const float4*>(&bias[2 * FH + lane * 4]);
    o.x = h2u(__floats2half2_rn(lrelu(acc2.x * inv2 + b.x), lrelu(acc2.y * inv2 + b.y)));
    o.y = h2u(__floats2half2_rn(lrelu(acc2.z * inv2 + b.z), lrelu(acc2.w * inv2 + b.w)));
    *reinterpret_cast<uint2*>(&xo[2 * FH]) = o;
    b = *reinterpret_cast<const float4*>(&bias[3 * FH + lane * 4]);
    o.x = h2u(__floats2half2_rn(lrelu(acc3.x * inv3 + b.x), lrelu(acc3.y * inv3 + b.y)));
    o.y = h2u(__floats2half2_rn(lrelu(acc3.z * inv3 + b.z), lrelu(acc3.w * inv3 + b.w)));
    *reinterpret_cast<uint2*>(&xo[3 * FH]) = o;
}

// ---------------- layer 2 fused gather: same depth-3 index pipeline ---------
__global__ void gather2_kernel(float* __restrict__ out, const float* __restrict__ bias_out) {
    long n = ((long)blockIdx.x * blockDim.x + threadIdx.x) >> 5;
    int lane = threadIdx.x & 31;
    if (n >= NN) return;

    const int beg = g_row[n];
    const int end = g_row[n + 1];
    const float sd = g_sdst2[n];

    float2 acc = make_float2(0.f, 0.f);
    float den = 0.f;

    float ssl[2];
    __half2 hvl[2];
    auto ldpay = [&](int slot, int s) {
        ssl[slot] = g_ssrc2[s];
        hvl[slot] = *reinterpret_cast<const __half2*>(&g_xs2h[(size_t)s * NC + lane * 2]);
    };

    int i0 = g_csrc[beg];
    int i1 = (beg + 1 < end) ? g_csrc[beg + 1] : i0;
    int i2 = (beg + 2 < end) ? g_csrc[beg + 2] : i1;
    ldpay(0, i0);
    ldpay(1, i1);

    for (int j = beg; j < end; j++) {
        const int slot = (j - beg) & 1;
        float ss = ssl[slot];
        __half2 hv = hvl[slot];
        ldpay(slot, i2);
        i0 = i1; i1 = i2;
        i2 = (j + 3 < end) ? g_csrc[j + 3] : i2;

        float ex = __expf(lrelu(ss + sd));
        float2 v = __half22float2(hv);
        den += ex;
        acc.x += ex * v.x; acc.y += ex * v.y;
    }
    const float inv = 1.f / den;
    const float2 b = *reinterpret_cast<const float2*>(&bias_out[lane * 2]);
    float2 o;
    o.x = tanhf(lrelu(acc.x * inv + b.x));
    o.y = tanhf(lrelu(acc.y * inv + b.y));
    *reinterpret_cast<float2*>(&out[(size_t)n * NC + lane * 2]) = o;
}

// ---------------- launch ----------------------------------------------------
extern "C" void kernel_launch(void* const* d_in, const int* in_sizes, int n_in,
                              void* d_out, int out_size) {
    const float* type_emb  = (const float*)d_in[0];  // [4,50000,128]
    const int*   edge      = (const int*)d_in[1];    // [2,800000]
    const float* W         = (const float*)d_in[2];  // [4,128,128]
    const float* att_src   = (const float*)d_in[3];  // [4,128]
    const float* att_dst   = (const float*)d_in[4];  // [4,128]
    const float* bias      = (const float*)d_in[5];  // [4,128]
    const float* W_out     = (const float*)d_in[6];  // [512,64]
    const float* att_src_o = (const float*)d_in[7];  // [64]
    const float* att_dst_o = (const float*)d_in[8];  // [64]
    const float* bias_o    = (const float*)d_in[9];  // [64]
    float* out = (float*)d_out;                      // [50000,64]
    (void)in_sizes; (void)n_in; (void)out_size;

    __half *p_xsh, *p_xh, *p_xs2h;
    float *p_ssrc, *p_sdst, *p_ssrc2, *p_sdst2;
    int *p_deg;
    cudaGetSymbolAddress((void**)&p_xsh, g_xsh);
    cudaGetSymbolAddress((void**)&p_xh, g_xh);
    cudaGetSymbolAddress((void**)&p_xs2h, g_xs2h);
    cudaGetSymbolAddress((void**)&p_ssrc, g_ssrc);
    cudaGetSymbolAddress((void**)&p_sdst, g_sdst);
    cudaGetSymbolAddress((void**)&p_ssrc2, g_ssrc2);
    cudaGetSymbolAddress((void**)&p_sdst2, g_sdst2);
    cudaGetSymbolAddress((void**)&p_deg, g_deg);

    constexpr int GEMM1_SMEM = 73728;   // 2*34816 + 2*2048

    // one-time host objects (created on the uncaptured correctness call)
    static cudaStream_t s_side = nullptr;
    static cudaEvent_t ev_fork = nullptr, ev_join = nullptr;
    if (s_side == nullptr) {
        cudaStreamCreateWithFlags(&s_side, cudaStreamNonBlocking);
        cudaEventCreateWithFlags(&ev_fork, cudaEventDisableTiming);
        cudaEventCreateWithFlags(&ev_join, cudaEventDisableTiming);
        cudaFuncSetAttribute(hgemm1_kernel,
                             cudaFuncAttributeMaxDynamicSharedMemorySize, GEMM1_SMEM);
    }

    // ---- fork: CSR build on side stream, overlapped with layer-1 GEMM ----
    cudaEventRecord(ev_fork, 0);
    cudaStreamWaitEvent(s_side, ev_fork, 0);
    cudaMemsetAsync(p_deg, 0, NN * sizeof(int), s_side);
    count_kernel<<<(ET + 255) / 256, 256, 0, s_side>>>(edge);
    scan_kernel<<<1, SCAN_T, 0, s_side>>>();
    fill_kernel<<<(ET + 255) / 256, 256, 0, s_side>>>(edge);
    cudaEventRecord(ev_join, s_side);

    // ---- Layer 1 GEMM (single-stage full-K, 512 thr, fused dots) ----
    dim3 g1((NN + 127) / 128, 1, NH);
    hgemm1_kernel<<<g1, 512, GEMM1_SMEM>>>(
        type_emb, W, p_xsh, p_ssrc, p_sdst, att_src, att_dst);

    // ---- join: gather needs CSR + GEMM ----
    cudaStreamWaitEvent(0, ev_join, 0);

    gather1_kernel<<<(int)(((long)NN * 32 + 255) / 256), 256>>>(bias);

    // ---- Layer 2: fp16 A GEMM, then gather ----
    dim3 g2((NN + 127) / 128, 1, 1);
    hgemm2_kernel<<<g2, 256>>>(
        p_xh, W_out, p_xs2h, p_ssrc2, p_sdst2, att_src_o, att_dst_o,
        NN, NH * FH);

    gather2_kernel<<<(NN * 32 + 255) / 256, 256>>>(out, bias_o);
}